// round 4
// baseline (speedup 1.0000x reference)
#include <cuda_runtime.h>
#include <math.h>

#define D   4096
#define H   64
#define S   64
#define EPSF 1e-5f

// Scratch (allocation-free rule: __device__ globals)
__device__ float g_mix[4 * D];    // [r, k, v, g] mixed input vectors
__device__ float g_rkvg[4 * D];   // [r, k, v, g] matvec results
__device__ float g_y[D];          // gated, normalized wkv -> input to Wo

// ---------------------------------------------------------------------------
// Kernel 1: LayerNorm(x) + 4 token-mixes. Single block, 256 threads.
// ---------------------------------------------------------------------------
__global__ __launch_bounds__(256) void ln_mix_kernel(
    const float* __restrict__ x, const float* __restrict__ state1,
    const float* __restrict__ tmr, const float* __restrict__ tmk,
    const float* __restrict__ tmv, const float* __restrict__ tmg,
    const float* __restrict__ ln1_w, const float* __restrict__ ln1_b,
    float* __restrict__ state1_out)
{
    int tid = threadIdx.x;
    float4 xv[4];
    float s = 0.f, sq = 0.f;
#pragma unroll
    for (int k = 0; k < 4; k++) {
        xv[k] = ((const float4*)x)[tid + k * 256];
        s  += xv[k].x + xv[k].y + xv[k].z + xv[k].w;
        sq += xv[k].x * xv[k].x + xv[k].y * xv[k].y
            + xv[k].z * xv[k].z + xv[k].w * xv[k].w;
    }
    __shared__ float sa[8], sb[8];
#pragma unroll
    for (int o = 16; o; o >>= 1) {
        s  += __shfl_xor_sync(0xffffffffu, s, o);
        sq += __shfl_xor_sync(0xffffffffu, sq, o);
    }
    int w = tid >> 5, l = tid & 31;
    if (l == 0) { sa[w] = s; sb[w] = sq; }
    __syncthreads();
    __shared__ float s_mean, s_rstd;
    if (tid == 0) {
        float ts = 0.f, tq = 0.f;
#pragma unroll
        for (int i = 0; i < 8; i++) { ts += sa[i]; tq += sb[i]; }
        float m   = ts * (1.0f / D);
        float var = tq * (1.0f / D) - m * m;
        s_mean = m;
        s_rstd = rsqrtf(var + EPSF);
    }
    __syncthreads();
    float m = s_mean, rstd = s_rstd;

#pragma unroll
    for (int k = 0; k < 4; k++) {
        int idx = tid + k * 256;
        float4 w4 = ((const float4*)ln1_w)[idx];
        float4 b4 = ((const float4*)ln1_b)[idx];
        float4 st = ((const float4*)state1)[idx];
        float4 xx;
        xx.x = (xv[k].x - m) * rstd * w4.x + b4.x;
        xx.y = (xv[k].y - m) * rstd * w4.y + b4.y;
        xx.z = (xv[k].z - m) * rstd * w4.z + b4.z;
        xx.w = (xv[k].w - m) * rstd * w4.w + b4.w;
        ((float4*)state1_out)[idx] = xx;

        const float* tms[4] = {tmr, tmk, tmv, tmg};
#pragma unroll
        for (int mi = 0; mi < 4; mi++) {
            float4 t = ((const float4*)tms[mi])[idx];
            float4 o;
            o.x = st.x * (1.f - t.x) + xx.x * t.x;
            o.y = st.y * (1.f - t.y) + xx.y * t.y;
            o.z = st.z * (1.f - t.z) + xx.z * t.z;
            o.w = st.w * (1.f - t.w) + xx.w * t.w;
            ((float4*)(g_mix + mi * D))[idx] = o;
        }
    }
}

// ---------------------------------------------------------------------------
// Kernel 2: fused 4x matvec (Wr,Wk,Wv,Wg). Warp-per-row, float4 streams.
// grid = (512, 4), block = 256 (8 warps -> 8 rows per block).
// ---------------------------------------------------------------------------
__global__ __launch_bounds__(256) void matvec4_kernel(
    const float* __restrict__ Wr, const float* __restrict__ Wk,
    const float* __restrict__ Wv, const float* __restrict__ Wg)
{
    __shared__ float sx[D];
    int m = blockIdx.y;
    const float* W  = (m == 0) ? Wr : (m == 1) ? Wk : (m == 2) ? Wv : Wg;
    const float* xv = g_mix + m * D;
    for (int i = threadIdx.x; i < D / 4; i += 256)
        ((float4*)sx)[i] = ((const float4*)xv)[i];
    __syncthreads();

    int warp = threadIdx.x >> 5, lane = threadIdx.x & 31;
    int row = blockIdx.x * 8 + warp;
    const float* Wrow = W + (size_t)row * D;
    float acc = 0.f;
#pragma unroll 8
    for (int j = lane * 4; j < D; j += 128) {
        float4 w4 = *(const float4*)(Wrow + j);
        float4 x4 = *(const float4*)(sx + j);
        acc += w4.x * x4.x + w4.y * x4.y + w4.z * x4.z + w4.w * x4.w;
    }
#pragma unroll
    for (int o = 16; o; o >>= 1) acc += __shfl_xor_sync(0xffffffffu, acc, o);
    if (lane == 0) g_rkvg[m * D + row] = acc;
}

// ---------------------------------------------------------------------------
// Kernel 3: per-head WKV + state2 update + InstanceNorm + SiLU gate.
// grid = 64 heads, block = 64 threads (thread j = output column).
// ---------------------------------------------------------------------------
__global__ __launch_bounds__(64) void wkv_kernel(
    const float* __restrict__ state2, const float* __restrict__ time_decay,
    const float* __restrict__ time_first, const float* __restrict__ lnx_w,
    const float* __restrict__ lnx_b, float* __restrict__ state2_out)
{
    int h = blockIdx.x, j = threadIdx.x;
    __shared__ float sk[S], sr[S], stf[S], sdec[S], swk[S];
    sr[j]   = g_rkvg[0 * D + h * S + j];
    sk[j]   = g_rkvg[1 * D + h * S + j];
    stf[j]  = time_first[h * S + j];
    sdec[j] = time_decay[h * S + j];
    float vj = g_rkvg[2 * D + h * S + j];
    __syncthreads();

    const float* S2  = state2     + (size_t)h * S * S;
    float*       S2o = state2_out + (size_t)h * S * S;
    float wkv = 0.f;
#pragma unroll 8
    for (int i = 0; i < S; i++) {
        float s2 = S2[i * S + j];
        float kv = sk[i] * vj;
        S2o[i * S + j] = kv + s2 * sdec[i];
        wkv += sr[i] * (kv * stf[i] + s2);
    }
    swk[j] = wkv;
    __syncthreads();

    float s = 0.f, sq = 0.f;
#pragma unroll
    for (int i = 0; i < S; i++) { float t = swk[i]; s += t; sq += t * t; }
    float mu  = s * (1.0f / S);
    float var = sq * (1.0f / S) - mu * mu;
    float xn  = (wkv - mu) * rsqrtf(var + EPSF);

    float g    = g_rkvg[3 * D + h * S + j];
    float gate = g / (1.f + expf(-g));   // SiLU
    g_y[h * S + j] = (xn * lnx_w[h * S + j] + lnx_b[h * S + j]) * gate;
}

// ---------------------------------------------------------------------------
// Kernel 4: out = x + Wo @ y. Warp-per-row.
// ---------------------------------------------------------------------------
__global__ __launch_bounds__(256) void matvec_out_kernel(
    const float* __restrict__ Wo, const float* __restrict__ x,
    float* __restrict__ out)
{
    __shared__ float sy[D];
    for (int i = threadIdx.x; i < D / 4; i += 256)
        ((float4*)sy)[i] = ((const float4*)g_y)[i];
    __syncthreads();

    int warp = threadIdx.x >> 5, lane = threadIdx.x & 31;
    int row = blockIdx.x * 8 + warp;
    const float* Wrow = Wo + (size_t)row * D;
    float acc = 0.f;
#pragma unroll 8
    for (int j = lane * 4; j < D; j += 128) {
        float4 w4 = *(const float4*)(Wrow + j);
        float4 y4 = *(const float4*)(sy + j);
        acc += w4.x * y4.x + w4.y * y4.y + w4.z * y4.z + w4.w * y4.w;
    }
#pragma unroll
    for (int o = 16; o; o >>= 1) acc += __shfl_xor_sync(0xffffffffu, acc, o);
    if (lane == 0) out[row] = x[row] + acc;
}

// ---------------------------------------------------------------------------
extern "C" void kernel_launch(void* const* d_in, const int* in_sizes, int n_in,
                              void* d_out, int out_size)
{
    const float* x      = (const float*)d_in[0];
    const float* state1 = (const float*)d_in[1];
    const float* state2 = (const float*)d_in[2];
    const float* tmk    = (const float*)d_in[3];
    const float* tmv    = (const float*)d_in[4];
    const float* tmr    = (const float*)d_in[5];
    const float* tmg    = (const float*)d_in[6];
    const float* tdec   = (const float*)d_in[7];
    const float* tfir   = (const float*)d_in[8];
    const float* Wr     = (const float*)d_in[9];
    const float* Wk     = (const float*)d_in[10];
    const float* Wv     = (const float*)d_in[11];
    const float* Wg     = (const float*)d_in[12];
    const float* Wo     = (const float*)d_in[13];
    const float* ln1w   = (const float*)d_in[14];
    const float* ln1b   = (const float*)d_in[15];
    const float* lnxw   = (const float*)d_in[16];
    const float* lnxb   = (const float*)d_in[17];

    float* out        = (float*)d_out;         // [0, D)
    float* state1_out = out + D;               // [D, 2D)
    float* state2_out = out + 2 * D;           // [2D, 2D + H*S*S)

    ln_mix_kernel<<<1, 256>>>(x, state1, tmr, tmk, tmv, tmg, ln1w, ln1b,
                              state1_out);
    matvec4_kernel<<<dim3(512, 4), 256>>>(Wr, Wk, Wv, Wg);
    wkv_kernel<<<64, 64>>>(state2, tdec, tfir, lnxw, lnxb, state2_out);
    matvec_out_kernel<<<512, 256>>>(Wo, x, out);
}

// round 5
// speedup vs baseline: 1.1594x; 1.1594x over previous
#include <cuda_runtime.h>
#include <math.h>

#define D   4096
#define H   64
#define S   64
#define EPSF 1e-5f

// Scratch (allocation-free rule: __device__ globals)
__device__ float g_mix[4 * D];    // [r, k, v, g] mixed input vectors
__device__ float g_rkvg[4 * D];   // [r, k, v, g] matvec results
__device__ float g_y[D];          // gated, normalized wkv -> input to Wo

// ---------------------------------------------------------------------------
// Kernel 1: LayerNorm(x) + 4 token-mixes. Single block, 256 threads.
// ---------------------------------------------------------------------------
__global__ __launch_bounds__(256) void ln_mix_kernel(
    const float* __restrict__ x, const float* __restrict__ state1,
    const float* __restrict__ tmr, const float* __restrict__ tmk,
    const float* __restrict__ tmv, const float* __restrict__ tmg,
    const float* __restrict__ ln1_w, const float* __restrict__ ln1_b,
    float* __restrict__ state1_out)
{
    int tid = threadIdx.x;
    float4 xv[4];
    float s = 0.f, sq = 0.f;
#pragma unroll
    for (int k = 0; k < 4; k++) {
        xv[k] = ((const float4*)x)[tid + k * 256];
        s  += xv[k].x + xv[k].y + xv[k].z + xv[k].w;
        sq += xv[k].x * xv[k].x + xv[k].y * xv[k].y
            + xv[k].z * xv[k].z + xv[k].w * xv[k].w;
    }
    __shared__ float sa[8], sb[8];
#pragma unroll
    for (int o = 16; o; o >>= 1) {
        s  += __shfl_xor_sync(0xffffffffu, s, o);
        sq += __shfl_xor_sync(0xffffffffu, sq, o);
    }
    int w = tid >> 5, l = tid & 31;
    if (l == 0) { sa[w] = s; sb[w] = sq; }
    __syncthreads();
    __shared__ float s_mean, s_rstd;
    if (tid == 0) {
        float ts = 0.f, tq = 0.f;
#pragma unroll
        for (int i = 0; i < 8; i++) { ts += sa[i]; tq += sb[i]; }
        float m   = ts * (1.0f / D);
        float var = tq * (1.0f / D) - m * m;
        s_mean = m;
        s_rstd = rsqrtf(var + EPSF);
    }
    __syncthreads();
    float m = s_mean, rstd = s_rstd;

#pragma unroll
    for (int k = 0; k < 4; k++) {
        int idx = tid + k * 256;
        float4 w4 = ((const float4*)ln1_w)[idx];
        float4 b4 = ((const float4*)ln1_b)[idx];
        float4 st = ((const float4*)state1)[idx];
        float4 xx;
        xx.x = (xv[k].x - m) * rstd * w4.x + b4.x;
        xx.y = (xv[k].y - m) * rstd * w4.y + b4.y;
        xx.z = (xv[k].z - m) * rstd * w4.z + b4.z;
        xx.w = (xv[k].w - m) * rstd * w4.w + b4.w;
        ((float4*)state1_out)[idx] = xx;

        const float* tms[4] = {tmr, tmk, tmv, tmg};
#pragma unroll
        for (int mi = 0; mi < 4; mi++) {
            float4 t = ((const float4*)tms[mi])[idx];
            float4 o;
            o.x = st.x * (1.f - t.x) + xx.x * t.x;
            o.y = st.y * (1.f - t.y) + xx.y * t.y;
            o.z = st.z * (1.f - t.z) + xx.z * t.z;
            o.w = st.w * (1.f - t.w) + xx.w * t.w;
            ((float4*)(g_mix + mi * D))[idx] = o;
        }
    }
}

// ---------------------------------------------------------------------------
// Quarter-row dot-product helper: warp computes dot over 1024 elements.
// Weights streamed with __ldcs (evict-first); vector via L1-cached LDG.
// ---------------------------------------------------------------------------
__device__ __forceinline__ float quarter_dot(const float* Wp, const float* xp)
{
    float a0 = 0.f, a1 = 0.f;
#pragma unroll
    for (int it = 0; it < 8; it += 2) {
        float4 w0 = __ldcs((const float4*)(Wp + it * 128));
        float4 x0 = *(const float4*)(xp + it * 128);
        float4 w1 = __ldcs((const float4*)(Wp + (it + 1) * 128));
        float4 x1 = *(const float4*)(xp + (it + 1) * 128);
        a0 += w0.x * x0.x + w0.y * x0.y + w0.z * x0.z + w0.w * x0.w;
        a1 += w1.x * x1.x + w1.y * x1.y + w1.z * x1.z + w1.w * x1.w;
    }
    float acc = a0 + a1;
#pragma unroll
    for (int o = 16; o; o >>= 1) acc += __shfl_xor_sync(0xffffffffu, acc, o);
    return acc;
}

// ---------------------------------------------------------------------------
// Kernel 2: fused 4x matvec (Wr,Wk,Wv,Wg). 4 warps per row, 2 rows per block.
// grid = (2048, 4), block = 256.
// ---------------------------------------------------------------------------
__global__ __launch_bounds__(256) void matvec4_kernel(
    const float* __restrict__ Wr, const float* __restrict__ Wk,
    const float* __restrict__ Wv, const float* __restrict__ Wg)
{
    int m = blockIdx.y;
    const float* W  = (m == 0) ? Wr : (m == 1) ? Wk : (m == 2) ? Wv : Wg;
    const float* xv = g_mix + m * D;

    int warp = threadIdx.x >> 5, lane = threadIdx.x & 31;
    int row  = blockIdx.x * 2 + (warp >> 2);
    int q    = warp & 3;
    const float* Wp = W  + (size_t)row * D + q * 1024 + lane * 4;
    const float* xp = xv + q * 1024 + lane * 4;

    float acc = quarter_dot(Wp, xp);

    __shared__ float part[8];
    if (lane == 0) part[warp] = acc;
    __syncthreads();
    if (threadIdx.x < 2) {
        int r = blockIdx.x * 2 + threadIdx.x;
        int b = threadIdx.x * 4;
        g_rkvg[m * D + r] = (part[b] + part[b + 1]) + (part[b + 2] + part[b + 3]);
    }
}

// ---------------------------------------------------------------------------
// Kernel 3: per-head WKV + state2 update + InstanceNorm + SiLU gate.
// grid = 64 heads, block = 256 threads (4-way parallel over i-dimension).
// ---------------------------------------------------------------------------
__global__ __launch_bounds__(256) void wkv_kernel(
    const float* __restrict__ state2, const float* __restrict__ time_decay,
    const float* __restrict__ time_first, const float* __restrict__ lnx_w,
    const float* __restrict__ lnx_b, float* __restrict__ state2_out)
{
    int h = blockIdx.x, t = threadIdx.x;
    int j = t & 63, ig = t >> 6;               // ig in [0,4): i-chunk
    __shared__ float sk[S], sr[S], stf[S], sdec[S];
    __shared__ float pw[256];
    __shared__ float sw[S];
    if (t < S) {
        sr[t]   = g_rkvg[0 * D + h * S + t];
        sk[t]   = g_rkvg[1 * D + h * S + t];
        stf[t]  = time_first[h * S + t];
        sdec[t] = time_decay[h * S + t];
    }
    float vj = g_rkvg[2 * D + h * S + j];
    __syncthreads();

    const float* S2  = state2     + (size_t)h * S * S;
    float*       S2o = state2_out + (size_t)h * S * S;
    float wkv = 0.f;
    int i0 = ig * 16;
#pragma unroll
    for (int di = 0; di < 16; di++) {
        int i = i0 + di;
        float s2 = S2[i * S + j];
        float kv = sk[i] * vj;
        S2o[i * S + j] = kv + s2 * sdec[i];
        wkv += sr[i] * (kv * stf[i] + s2);
    }
    pw[t] = wkv;
    __syncthreads();

    if (t < S) {
        float w = (pw[j] + pw[64 + j]) + (pw[128 + j] + pw[192 + j]);
        sw[j] = w;
    }
    __syncthreads();
    if (t < S) {
        float s = 0.f, sq = 0.f;
#pragma unroll
        for (int i = 0; i < S; i++) { float u = sw[i]; s += u; sq += u * u; }
        float mu  = s * (1.0f / S);
        float var = sq * (1.0f / S) - mu * mu;
        float xn  = (sw[j] - mu) * rsqrtf(var + EPSF);

        float g    = g_rkvg[3 * D + h * S + j];
        float gate = g / (1.f + expf(-g));   // SiLU
        g_y[h * S + j] = (xn * lnx_w[h * S + j] + lnx_b[h * S + j]) * gate;
    }
}

// ---------------------------------------------------------------------------
// Kernel 4: out = x + Wo @ y. 4 warps per row, 2 rows per block. grid = 2048.
// ---------------------------------------------------------------------------
__global__ __launch_bounds__(256) void matvec_out_kernel(
    const float* __restrict__ Wo, const float* __restrict__ x,
    float* __restrict__ out)
{
    int warp = threadIdx.x >> 5, lane = threadIdx.x & 31;
    int row  = blockIdx.x * 2 + (warp >> 2);
    int q    = warp & 3;
    const float* Wp = Wo  + (size_t)row * D + q * 1024 + lane * 4;
    const float* yp = g_y + q * 1024 + lane * 4;

    float acc = quarter_dot(Wp, yp);

    __shared__ float part[8];
    if (lane == 0) part[warp] = acc;
    __syncthreads();
    if (threadIdx.x < 2) {
        int r = blockIdx.x * 2 + threadIdx.x;
        int b = threadIdx.x * 4;
        out[r] = x[r] + (part[b] + part[b + 1]) + (part[b + 2] + part[b + 3]);
    }
}

// ---------------------------------------------------------------------------
extern "C" void kernel_launch(void* const* d_in, const int* in_sizes, int n_in,
                              void* d_out, int out_size)
{
    const float* x      = (const float*)d_in[0];
    const float* state1 = (const float*)d_in[1];
    const float* state2 = (const float*)d_in[2];
    const float* tmk    = (const float*)d_in[3];
    const float* tmv    = (const float*)d_in[4];
    const float* tmr    = (const float*)d_in[5];
    const float* tmg    = (const float*)d_in[6];
    const float* tdec   = (const float*)d_in[7];
    const float* tfir   = (const float*)d_in[8];
    const float* Wr     = (const float*)d_in[9];
    const float* Wk     = (const float*)d_in[10];
    const float* Wv     = (const float*)d_in[11];
    const float* Wg     = (const float*)d_in[12];
    const float* Wo     = (const float*)d_in[13];
    const float* ln1w   = (const float*)d_in[14];
    const float* ln1b   = (const float*)d_in[15];
    const float* lnxw   = (const float*)d_in[16];
    const float* lnxb   = (const float*)d_in[17];

    float* out        = (float*)d_out;         // [0, D)
    float* state1_out = out + D;               // [D, 2D)
    float* state2_out = out + 2 * D;           // [2D, 2D + H*S*S)

    ln_mix_kernel<<<1, 256>>>(x, state1, tmr, tmk, tmv, tmg, ln1w, ln1b,
                              state1_out);
    matvec4_kernel<<<dim3(2048, 4), 256>>>(Wr, Wk, Wv, Wg);
    wkv_kernel<<<64, 256>>>(state2, tdec, tfir, lnxw, lnxb, state2_out);
    matvec_out_kernel<<<2048, 256>>>(Wo, x, out);
}

// round 6
// speedup vs baseline: 1.2538x; 1.0814x over previous
#include <cuda_runtime.h>
#include <math.h>

#define D   4096
#define H   64
#define S   64
#define EPSF 1e-5f

// Scratch (allocation-free rule: __device__ globals)
__device__ float g_mix[4 * D];    // [r, k, v, g] mixed input vectors
__device__ float g_rkvg[4 * D];   // [r, k, v, g] matvec results
__device__ float g_y[D];          // gated, normalized wkv -> input to Wo

// ---------------------------------------------------------------------------
// Kernel 1: LayerNorm(x) + 4 token-mixes. Single block, 256 threads.
// ---------------------------------------------------------------------------
__global__ __launch_bounds__(256) void ln_mix_kernel(
    const float* __restrict__ x, const float* __restrict__ state1,
    const float* __restrict__ tmr, const float* __restrict__ tmk,
    const float* __restrict__ tmv, const float* __restrict__ tmg,
    const float* __restrict__ ln1_w, const float* __restrict__ ln1_b,
    float* __restrict__ state1_out)
{
    int tid = threadIdx.x;
    float4 xv[4];
    float s = 0.f, sq = 0.f;
#pragma unroll
    for (int k = 0; k < 4; k++) {
        xv[k] = ((const float4*)x)[tid + k * 256];
        s  += xv[k].x + xv[k].y + xv[k].z + xv[k].w;
        sq += xv[k].x * xv[k].x + xv[k].y * xv[k].y
            + xv[k].z * xv[k].z + xv[k].w * xv[k].w;
    }
    __shared__ float sa[8], sb[8];
#pragma unroll
    for (int o = 16; o; o >>= 1) {
        s  += __shfl_xor_sync(0xffffffffu, s, o);
        sq += __shfl_xor_sync(0xffffffffu, sq, o);
    }
    int w = tid >> 5, l = tid & 31;
    if (l == 0) { sa[w] = s; sb[w] = sq; }
    __syncthreads();
    __shared__ float s_mean, s_rstd;
    if (tid == 0) {
        float ts = 0.f, tq = 0.f;
#pragma unroll
        for (int i = 0; i < 8; i++) { ts += sa[i]; tq += sb[i]; }
        float m   = ts * (1.0f / D);
        float var = tq * (1.0f / D) - m * m;
        s_mean = m;
        s_rstd = rsqrtf(var + EPSF);
    }
    __syncthreads();
    float m = s_mean, rstd = s_rstd;

#pragma unroll
    for (int k = 0; k < 4; k++) {
        int idx = tid + k * 256;
        float4 w4 = ((const float4*)ln1_w)[idx];
        float4 b4 = ((const float4*)ln1_b)[idx];
        float4 st = ((const float4*)state1)[idx];
        float4 xx;
        xx.x = (xv[k].x - m) * rstd * w4.x + b4.x;
        xx.y = (xv[k].y - m) * rstd * w4.y + b4.y;
        xx.z = (xv[k].z - m) * rstd * w4.z + b4.z;
        xx.w = (xv[k].w - m) * rstd * w4.w + b4.w;
        ((float4*)state1_out)[idx] = xx;

        const float* tms[4] = {tmr, tmk, tmv, tmg};
#pragma unroll
        for (int mi = 0; mi < 4; mi++) {
            float4 t = ((const float4*)tms[mi])[idx];
            float4 o;
            o.x = st.x * (1.f - t.x) + xx.x * t.x;
            o.y = st.y * (1.f - t.y) + xx.y * t.y;
            o.z = st.z * (1.f - t.z) + xx.z * t.z;
            o.w = st.w * (1.f - t.w) + xx.w * t.w;
            ((float4*)(g_mix + mi * D))[idx] = o;
        }
    }
}

// ---------------------------------------------------------------------------
// Eighth-row dot-product: warp computes dot over 512 elements (4 LDG.128
// weight loads, issued up front for max MLP). Weights evict-first (__ldcs).
// ---------------------------------------------------------------------------
__device__ __forceinline__ float eighth_dot(const float* Wp, const float* xp)
{
    float4 w0 = __ldcs((const float4*)(Wp + 0 * 128));
    float4 w1 = __ldcs((const float4*)(Wp + 1 * 128));
    float4 w2 = __ldcs((const float4*)(Wp + 2 * 128));
    float4 w3 = __ldcs((const float4*)(Wp + 3 * 128));
    float4 x0 = *(const float4*)(xp + 0 * 128);
    float4 x1 = *(const float4*)(xp + 1 * 128);
    float4 x2 = *(const float4*)(xp + 2 * 128);
    float4 x3 = *(const float4*)(xp + 3 * 128);
    float a0 = w0.x * x0.x + w0.y * x0.y + w0.z * x0.z + w0.w * x0.w;
    float a1 = w1.x * x1.x + w1.y * x1.y + w1.z * x1.z + w1.w * x1.w;
    float a2 = w2.x * x2.x + w2.y * x2.y + w2.z * x2.z + w2.w * x2.w;
    float a3 = w3.x * x3.x + w3.y * x3.y + w3.z * x3.z + w3.w * x3.w;
    float acc = (a0 + a1) + (a2 + a3);
#pragma unroll
    for (int o = 16; o; o >>= 1) acc += __shfl_xor_sync(0xffffffffu, acc, o);
    return acc;
}

// ---------------------------------------------------------------------------
// Kernel 2: fused 4x matvec (Wr,Wk,Wv,Wg). One row per block, 8 warps/row.
// grid = (4096, 4), block = 256.
// ---------------------------------------------------------------------------
__global__ __launch_bounds__(256) void matvec4_kernel(
    const float* __restrict__ Wr, const float* __restrict__ Wk,
    const float* __restrict__ Wv, const float* __restrict__ Wg)
{
    int m = blockIdx.y;
    const float* W  = (m == 0) ? Wr : (m == 1) ? Wk : (m == 2) ? Wv : Wg;
    const float* xv = g_mix + m * D;

    int warp = threadIdx.x >> 5, lane = threadIdx.x & 31;
    int row  = blockIdx.x;
    const float* Wp = W  + (size_t)row * D + warp * 512 + lane * 4;
    const float* xp = xv + warp * 512 + lane * 4;

    float acc = eighth_dot(Wp, xp);

    __shared__ float part[8];
    if (lane == 0) part[warp] = acc;
    __syncthreads();
    if (threadIdx.x == 0) {
        float r = ((part[0] + part[1]) + (part[2] + part[3]))
                + ((part[4] + part[5]) + (part[6] + part[7]));
        g_rkvg[m * D + row] = r;
    }
}

// ---------------------------------------------------------------------------
// Kernel 3: per-head WKV + state2 update + InstanceNorm + SiLU gate.
// grid = 64 heads, block = 256 threads (4-way parallel over i-dimension).
// ---------------------------------------------------------------------------
__global__ __launch_bounds__(256) void wkv_kernel(
    const float* __restrict__ state2, const float* __restrict__ time_decay,
    const float* __restrict__ time_first, const float* __restrict__ lnx_w,
    const float* __restrict__ lnx_b, float* __restrict__ state2_out)
{
    int h = blockIdx.x, t = threadIdx.x;
    int j = t & 63, ig = t >> 6;               // ig in [0,4): i-chunk
    __shared__ float sk[S], sr[S], stf[S], sdec[S];
    __shared__ float pw[256];
    __shared__ float sw[S];
    if (t < S) {
        sr[t]   = g_rkvg[0 * D + h * S + t];
        sk[t]   = g_rkvg[1 * D + h * S + t];
        stf[t]  = time_first[h * S + t];
        sdec[t] = time_decay[h * S + t];
    }
    float vj = g_rkvg[2 * D + h * S + j];
    __syncthreads();

    const float* S2  = state2     + (size_t)h * S * S;
    float*       S2o = state2_out + (size_t)h * S * S;
    float wkv = 0.f;
    int i0 = ig * 16;
#pragma unroll
    for (int di = 0; di < 16; di++) {
        int i = i0 + di;
        float s2 = S2[i * S + j];
        float kv = sk[i] * vj;
        S2o[i * S + j] = kv + s2 * sdec[i];
        wkv += sr[i] * (kv * stf[i] + s2);
    }
    pw[t] = wkv;
    __syncthreads();

    if (t < S) {
        float w = (pw[j] + pw[64 + j]) + (pw[128 + j] + pw[192 + j]);
        sw[j] = w;
    }
    __syncthreads();
    if (t < S) {
        float s = 0.f, sq = 0.f;
#pragma unroll
        for (int i = 0; i < S; i++) { float u = sw[i]; s += u; sq += u * u; }
        float mu  = s * (1.0f / S);
        float var = sq * (1.0f / S) - mu * mu;
        float xn  = (sw[j] - mu) * rsqrtf(var + EPSF);

        float g    = g_rkvg[3 * D + h * S + j];
        float gate = g / (1.f + expf(-g));   // SiLU
        g_y[h * S + j] = (xn * lnx_w[h * S + j] + lnx_b[h * S + j]) * gate;
    }
}

// ---------------------------------------------------------------------------
// Kernel 4: out = x + Wo @ y. One row per block, 8 warps/row. grid = 4096.
// ---------------------------------------------------------------------------
__global__ __launch_bounds__(256) void matvec_out_kernel(
    const float* __restrict__ Wo, const float* __restrict__ x,
    float* __restrict__ out)
{
    int warp = threadIdx.x >> 5, lane = threadIdx.x & 31;
    int row  = blockIdx.x;
    const float* Wp = Wo  + (size_t)row * D + warp * 512 + lane * 4;
    const float* yp = g_y + warp * 512 + lane * 4;

    float acc = eighth_dot(Wp, yp);

    __shared__ float part[8];
    if (lane == 0) part[warp] = acc;
    __syncthreads();
    if (threadIdx.x == 0) {
        float r = ((part[0] + part[1]) + (part[2] + part[3]))
                + ((part[4] + part[5]) + (part[6] + part[7]));
        out[row] = x[row] + r;
    }
}

// ---------------------------------------------------------------------------
extern "C" void kernel_launch(void* const* d_in, const int* in_sizes, int n_in,
                              void* d_out, int out_size)
{
    const float* x      = (const float*)d_in[0];
    const float* state1 = (const float*)d_in[1];
    const float* state2 = (const float*)d_in[2];
    const float* tmk    = (const float*)d_in[3];
    const float* tmv    = (const float*)d_in[4];
    const float* tmr    = (const float*)d_in[5];
    const float* tmg    = (const float*)d_in[6];
    const float* tdec   = (const float*)d_in[7];
    const float* tfir   = (const float*)d_in[8];
    const float* Wr     = (const float*)d_in[9];
    const float* Wk     = (const float*)d_in[10];
    const float* Wv     = (const float*)d_in[11];
    const float* Wg     = (const float*)d_in[12];
    const float* Wo     = (const float*)d_in[13];
    const float* ln1w   = (const float*)d_in[14];
    const float* ln1b   = (const float*)d_in[15];
    const float* lnxw   = (const float*)d_in[16];
    const float* lnxb   = (const float*)d_in[17];

    float* out        = (float*)d_out;         // [0, D)
    float* state1_out = out + D;               // [D, 2D)
    float* state2_out = out + 2 * D;           // [2D, 2D + H*S*S)

    ln_mix_kernel<<<1, 256>>>(x, state1, tmr, tmk, tmv, tmg, ln1w, ln1b,
                              state1_out);
    matvec4_kernel<<<dim3(4096, 4), 256>>>(Wr, Wk, Wv, Wg);
    wkv_kernel<<<64, 256>>>(state2, tdec, tfir, lnxw, lnxb, state2_out);
    matvec_out_kernel<<<4096, 256>>>(Wo, x, out);
}